// round 1
// baseline (speedup 1.0000x reference)
#include <cuda_runtime.h>
#include <cuda_bf16.h>

// Problem constants (fixed by dataset)
#define NB    16      // batch N
#define INCC  32      // input channels
#define INNX  65536   // input nodes
#define OUTCC 32      // output channels
#define OUTNX 8192    // output nodes
#define MAXD  16      // neighbors per output node
#define NF    512     // NB*INCC feature columns
#define OB    16      // output nodes per CTA in gather kernel

// 128 MB scratch for the transposed feature table feat[inn][j] = x[n,c,inn]*weight[c,inn]
__device__ float g_feat[(size_t)INNX * NF];

// ---------------------------------------------------------------------------
// Kernel 1: fused scale + transpose.  x is (512, 65536) row-major logically
// (j = n*32+c outer, inn inner); we want feat as (65536, 512).
// Standard 32x32 smem tile, 32x8 threads, padded to avoid bank conflicts.
// ---------------------------------------------------------------------------
__global__ __launch_bounds__(256) void prep_kernel(const float* __restrict__ x,
                                                   const float* __restrict__ w) {
    __shared__ float tile[32][33];
    const int inn0 = blockIdx.x << 5;
    const int j0   = blockIdx.y << 5;
    const int tx = threadIdx.x, ty = threadIdx.y;

    const int inn = inn0 + tx;
#pragma unroll
    for (int r = 0; r < 32; r += 8) {
        const int j = j0 + ty + r;
        const int c = j & 31;
        tile[ty + r][tx] = x[(size_t)j * INNX + inn] * w[(size_t)c * INNX + inn];
    }
    __syncthreads();
#pragma unroll
    for (int r = 0; r < 32; r += 8) {
        const int inn2 = inn0 + ty + r;
        const int j    = j0 + tx;
        g_feat[(size_t)inn2 * NF + j] = tile[tx][ty + r];
    }
}

// ---------------------------------------------------------------------------
// Kernel 2: gather + weighted pool + 32x32 GEMM + bias + transposed store.
// One CTA handles OB=16 consecutive output nodes; 256 threads.
//   - gather: thread t accumulates feature columns t and t+256 over 16 rows
//     (each row read is a fully-coalesced 2KB burst)
//   - GEMM: pooled (512) in smem (warp-broadcast reads), ct_weight transposed
//     in smem (conflict-free)
//   - output staged in smem [512][OB+1] so the global store of the
//     (N, OUTC, OUTN) layout is coalesced 64B segments
// A dtype (int64 vs int32) detected at runtime (JAX x64 canonicalization).
// ---------------------------------------------------------------------------
__global__ __launch_bounds__(256) void gather_kernel(
    const void* __restrict__ Araw,
    const float* __restrict__ mask,
    const float* __restrict__ mw,
    const float* __restrict__ ctw,
    const float* __restrict__ ctb,
    const float* __restrict__ bias,
    float* __restrict__ out)
{
    __shared__ float     s_ctw_t[OUTCC * INCC];   // [c][dout]
    __shared__ float     s_ctb[OUTCC];
    __shared__ float     s_pooled[NF];
    __shared__ float     s_stage[NF][OB + 1];
    __shared__ int       sA[MAXD];
    __shared__ float     sW[MAXD];
    __shared__ int       s_is64;

    const int tid = threadIdx.x;

    // Detect A dtype: if stored as int64, all values < 65536; if it's actually
    // int32 data read as int64, high words are (almost surely) nonzero indices.
    if (tid == 0) {
        const long long* a64 = (const long long*)Araw;
        int is64 = 1;
#pragma unroll
        for (int i = 0; i < 8; i++)
            if ((unsigned long long)a64[i] >= (unsigned long long)INNX) is64 = 0;
        s_is64 = is64;
    }

    // ct_weight transposed into smem; ct_bias
    for (int i = tid; i < OUTCC * INCC; i += 256) {
        const int dout = i >> 5, c = i & 31;
        s_ctw_t[c * OUTCC + dout] = ctw[i];
    }
    if (tid < OUTCC) s_ctb[tid] = ctb[tid];

    const int o_base = blockIdx.x * OB;

    for (int ol = 0; ol < OB; ol++) {
        const int o = o_base + ol;
        if (tid < MAXD) {
            // index + combined pooling weight
            sW[tid] = mw[o * MAXD + tid] * mask[o * MAXD + tid];
        }
        __syncthreads();  // also covers s_is64 / s_ctw_t on first iteration
        if (tid < MAXD) {
            sA[tid] = s_is64 ? (int)((const long long*)Araw)[(size_t)o * MAXD + tid]
                             : ((const int*)Araw)[(size_t)o * MAXD + tid];
        }
        __syncthreads();

        // gather + pool
        float acc0 = 0.f, acc1 = 0.f;
#pragma unroll
        for (int d = 0; d < MAXD; d++) {
            const float* row = g_feat + (size_t)sA[d] * NF;
            const float  wd  = sW[d];
            acc0 += wd * __ldg(row + tid);
            acc1 += wd * __ldg(row + tid + 256);
        }
        s_pooled[tid]       = acc0;
        s_pooled[tid + 256] = acc1;
        __syncthreads();

        // per-(n,dout) 32-length dot product
#pragma unroll
        for (int k = 0; k < 2; k++) {
            const int idx  = tid + 256 * k;
            const int n    = idx >> 5;
            const int dout = idx & 31;
            float s = s_ctb[dout];
            const float* p = s_pooled + n * INCC;
#pragma unroll
            for (int c = 0; c < INCC; c++)
                s += p[c] * s_ctw_t[c * OUTCC + dout];
            s_stage[idx][ol] = s;
        }
        __syncthreads();
    }

    // coalesced write-out: out[(n*32+dout)*8192 + o] = stage + bias[dout][o]
    for (int e = tid; e < NF * OB; e += 256) {
        const int row  = e >> 4;        // OB == 16
        const int col  = e & 15;
        const int o    = o_base + col;
        const int dout = row & 31;
        out[(size_t)row * OUTNX + o] = s_stage[row][col] + bias[(size_t)dout * OUTNX + o];
    }
}

extern "C" void kernel_launch(void* const* d_in, const int* in_sizes, int n_in,
                              void* d_out, int out_size) {
    const float* x    = (const float*)d_in[0];
    const void*  A    = d_in[1];                  // int64 or int32, detected on device
    const float* w    = (const float*)d_in[2];
    const float* mask = (const float*)d_in[3];
    const float* mw   = (const float*)d_in[4];
    const float* ctw  = (const float*)d_in[5];
    const float* ctb  = (const float*)d_in[6];
    const float* bias = (const float*)d_in[7];
    float* out = (float*)d_out;

    float* feat_ptr = nullptr; // only to force symbol use; kernels reference g_feat directly
    (void)feat_ptr; (void)in_sizes; (void)n_in; (void)out_size;

    dim3 pgrid(INNX / 32, NF / 32);
    dim3 pblk(32, 8);
    prep_kernel<<<pgrid, pblk>>>(x, w);

    gather_kernel<<<OUTNX / OB, 256>>>(A, mask, mw, ctw, ctb, bias, out);
}

// round 2
// speedup vs baseline: 1.4522x; 1.4522x over previous
#include <cuda_runtime.h>
#include <cuda_fp16.h>

// Problem constants (fixed by dataset)
#define NB    16
#define INCC  32
#define INNX  65536
#define OUTCC 32
#define OUTNX 8192
#define MAXD  16
#define NF    512     // NB*INCC feature columns
#define OB    8       // output nodes per CTA (one per warp)

// 64 MB fp16 feature table: feat[inn][j] = x[n,c,inn]*weight[c,inn], j = n*32+c
__device__ __half g_feat_h[(size_t)INNX * NF];

// ---------------------------------------------------------------------------
// Kernel 1: fused scale + transpose + fp32->fp16.
// x logically (512, 65536); feat (65536, 512) in fp16. 32x32 smem tile.
// ---------------------------------------------------------------------------
__global__ __launch_bounds__(256) void prep_kernel(const float* __restrict__ x,
                                                   const float* __restrict__ w) {
    __shared__ float tile[32][33];
    const int inn0 = blockIdx.x << 5;
    const int j0   = blockIdx.y << 5;
    const int tx = threadIdx.x, ty = threadIdx.y;

    const int inn = inn0 + tx;
#pragma unroll
    for (int r = 0; r < 32; r += 8) {
        const int j = j0 + ty + r;
        const int c = j & 31;
        tile[ty + r][tx] = x[(size_t)j * INNX + inn] * w[(size_t)c * INNX + inn];
    }
    __syncthreads();

    // half2 stores: i in [0,512): inn_local = i>>4, jh = i&15 (half2 col)
    __half2* out2 = (__half2*)g_feat_h;   // row stride = 256 half2
    const int tid = ty * 32 + tx;
#pragma unroll
    for (int k = 0; k < 2; k++) {
        const int i     = tid + 256 * k;
        const int inn_l = i >> 4;
        const int jh    = i & 15;
        const float a = tile[2 * jh][inn_l];
        const float b = tile[2 * jh + 1][inn_l];
        out2[(size_t)(inn0 + inn_l) * 256 + (j0 >> 1) + jh] = __floats2half2_rn(a, b);
    }
}

// ---------------------------------------------------------------------------
// Kernel 2: warp-per-output-node gather + pool + register GEMM + staged store.
// 256 threads = 8 warps = 8 output nodes per CTA. No CTA sync in main loop.
// ---------------------------------------------------------------------------
__global__ __launch_bounds__(256) void gather_kernel(
    const void*  __restrict__ Araw,
    const float* __restrict__ mask,
    const float* __restrict__ mw,
    const float* __restrict__ ctw,
    const float* __restrict__ ctb,
    const float* __restrict__ bias,
    float* __restrict__ out)
{
    __shared__ float s_pool[8][NF];          // per-warp pooled vector (16 KB)
    __shared__ float s_stage[NF][OB + 1];    // output staging (18 KB)
    __shared__ int   s_is64;

    const int tid  = threadIdx.x;
    const int w    = tid >> 5;
    const int lane = tid & 31;

    if (tid == 0) {
        const long long* a64 = (const long long*)Araw;
        int is64 = 1;
#pragma unroll
        for (int i = 0; i < 8; i++)
            if ((unsigned long long)a64[i] >= (unsigned long long)INNX) is64 = 0;
        s_is64 = is64;
    }
    __syncthreads();
    const int is64 = s_is64;

    // per-lane ct_weight row (dout = lane) and ct_bias in registers
    float wreg[32];
    {
        const float4* cw4 = (const float4*)(ctw + lane * INCC);
#pragma unroll
        for (int q = 0; q < 8; q++) {
            float4 v = cw4[q];
            wreg[4 * q + 0] = v.x; wreg[4 * q + 1] = v.y;
            wreg[4 * q + 2] = v.z; wreg[4 * q + 3] = v.w;
        }
    }
    const float cb = ctb[lane];

    const int o_base = blockIdx.x * OB;
    const int o      = o_base + w;

    // neighbor indices + pooling weights, distributed in lanes 0..15
    int   av = 0;
    float wv = 0.f;
    if (lane < MAXD) {
        av = is64 ? (int)((const long long*)Araw)[(size_t)o * MAXD + lane]
                  : ((const int*)Araw)[(size_t)o * MAXD + lane];
        wv = mw[o * MAXD + lane] * mask[o * MAXD + lane];
    }

    // ---- gather + pool: lane handles uint4 cols {lane, lane+32} of 64 ----
    const uint4* feat4 = (const uint4*)g_feat_h;   // row stride = 64 uint4
    float acc[16];
#pragma unroll
    for (int i = 0; i < 16; i++) acc[i] = 0.f;

#pragma unroll
    for (int d = 0; d < MAXD; d++) {
        const int   idx = __shfl_sync(0xffffffffu, av, d);
        const float wd  = __shfl_sync(0xffffffffu, wv, d);
        const uint4* row = feat4 + (size_t)idx * 64;
        uint4 u0 = row[lane];
        uint4 u1 = row[lane + 32];
        const __half2* h0 = (const __half2*)&u0;
        const __half2* h1 = (const __half2*)&u1;
#pragma unroll
        for (int q = 0; q < 4; q++) {
            float2 f0 = __half22float2(h0[q]);
            float2 f1 = __half22float2(h1[q]);
            acc[2 * q + 0] += wd * f0.x;
            acc[2 * q + 1] += wd * f0.y;
            acc[8 + 2 * q + 0] += wd * f1.x;
            acc[8 + 2 * q + 1] += wd * f1.y;
        }
    }

    // pooled -> smem (float4); uint4 col c covers half cols [8c, 8c+8)
    float4* sp4 = (float4*)s_pool[w];
    sp4[lane * 2 + 0]        = make_float4(acc[0], acc[1], acc[2], acc[3]);
    sp4[lane * 2 + 1]        = make_float4(acc[4], acc[5], acc[6], acc[7]);
    sp4[(lane + 32) * 2 + 0] = make_float4(acc[8], acc[9], acc[10], acc[11]);
    sp4[(lane + 32) * 2 + 1] = make_float4(acc[12], acc[13], acc[14], acc[15]);
    __syncwarp();

    // ---- GEMM: y[n=t][dout=lane] = ctb + sum_c pooled[t*32+c]*ctw[lane][c] ----
#pragma unroll
    for (int t = 0; t < NB; t++) {
        float y = cb;
#pragma unroll
        for (int c4 = 0; c4 < 8; c4++) {
            float4 p = sp4[t * 8 + c4];        // warp-broadcast LDS.128
            y += p.x * wreg[4 * c4 + 0] + p.y * wreg[4 * c4 + 1]
               + p.z * wreg[4 * c4 + 2] + p.w * wreg[4 * c4 + 3];
        }
        s_stage[t * 32 + lane][w] = y;
    }
    __syncthreads();

    // ---- coalesced write-out: out[row*8192 + o] = stage + bias ----
#pragma unroll
    for (int e = tid; e < NF * OB; e += 256) {
        const int row  = e >> 3;       // OB == 8
        const int col  = e & 7;
        const int oo   = o_base + col;
        const int dout = row & 31;
        out[(size_t)row * OUTNX + oo] = s_stage[row][col] + bias[(size_t)dout * OUTNX + oo];
    }
}

extern "C" void kernel_launch(void* const* d_in, const int* in_sizes, int n_in,
                              void* d_out, int out_size) {
    const float* x    = (const float*)d_in[0];
    const void*  A    = d_in[1];
    const float* w    = (const float*)d_in[2];
    const float* mask = (const float*)d_in[3];
    const float* mw   = (const float*)d_in[4];
    const float* ctw  = (const float*)d_in[5];
    const float* ctb  = (const float*)d_in[6];
    const float* bias = (const float*)d_in[7];
    float* out = (float*)d_out;
    (void)in_sizes; (void)n_in; (void)out_size;

    dim3 pgrid(INNX / 32, NF / 32);
    dim3 pblk(32, 8);
    prep_kernel<<<pgrid, pblk>>>(x, w);

    gather_kernel<<<OUTNX / OB, 256>>>(A, mask, mw, ctw, ctb, bias, out);
}